// round 8
// baseline (speedup 1.0000x reference)
#include <cuda_runtime.h>
#include <math.h>

#define BATCH    64
#define NLEN     1500
#define NFREQ    1251
#define NFREQ_P  1252                               // padded row (16B-aligned rows)
#define FCHUNK   64
#define NCHUNKS  ((NFREQ + FCHUNK - 1) / FCHUNK)    // 20
#define SEG      8
#define SEGLEN   188                                // 8*188 = 1504 >= 1500
#define NPAD     (SEG * SEGLEN)                     // 1504
#define SEGU2    (SEGLEN / 2)                       // 94 ulonglong2 per segment

__device__ float        g_psd[BATCH * NFREQ_P];
__device__ float        g_per[BATCH];
__device__ unsigned int g_pair_ticket[BATCH / 2];   // zero-init; self-resetting
__device__ unsigned int g_ticket;                   // zero-init; self-resetting

// ---- packed f32x2 helpers (sm_103a) ----
__device__ __forceinline__ unsigned long long pk2(float lo, float hi) {
    unsigned long long r;
    asm("mov.b64 %0, {%1, %2};" : "=l"(r) : "f"(lo), "f"(hi));
    return r;
}
__device__ __forceinline__ void upk2(unsigned long long v, float& lo, float& hi) {
    asm("mov.b64 {%0, %1}, %2;" : "=f"(lo), "=f"(hi) : "l"(v));
}
__device__ __forceinline__ unsigned long long fma2(unsigned long long a,
                                                   unsigned long long b,
                                                   unsigned long long c) {
    unsigned long long d;
    asm("fma.rn.f32x2 %0, %1, %2, %3;" : "=l"(d) : "l"(a), "l"(b), "l"(c));
    return d;
}

// Frequency grid value, matching jnp.arange semantics: iota*step + start in f32
__device__ __forceinline__ float grid_f(int i) {
    return __fadd_rn(__fmul_rn((float)i, 0.002f), 0.5f);
}

// ============================================================================
// Single fused kernel:
//  Stage 1 (all 640 blocks): segmented Goertzel PSD -> g_psd.
//  Stage 2 (last block per batch pair, via ticket): log-softmax-at-argmin for
//          both batches of the pair -> g_per.
//  Stage 3 (last pair overall, via ticket): mean over 64 -> out.
// Tickets self-reset so the kernel is graph-replay safe.
// ============================================================================
__global__ void __launch_bounds__(256)
fused_kernel(const float* __restrict__ x, const float* __restrict__ fs,
             const float* __restrict__ f_true, float* __restrict__ out)
{
    // +2 spare entries: tail prefetch may read one element past the last segment
    __shared__ __align__(16) char smem_raw[(NPAD / 2 + 2) * 16];
    ulonglong2* sx2 = (ulonglong2*)smem_raw;
    float4*     red = (float4*)smem_raw;     // overlaid AFTER sx2 is dead

    __shared__ float sredA[8], sredB[8], sbd[8];
    __shared__ int   sidx[8];
    __shared__ float sM2[2], sS2[2];
    __shared__ int   sflag;

    const int tid = threadIdx.x;
    const int bp  = blockIdx.y;              // batch pair 0..31
    const int b0  = 2 * bp;
    const int b1  = 2 * bp + 1;

    const int fl  = tid & (FCHUNK - 1);      // frequency lane 0..63
    const int sp  = tid >> 6;                // segment pair 0..3
    const int f   = blockIdx.x * FCHUNK + fl;
    const int fc  = (f < NFREQ) ? f : (NFREQ - 1);
    const float fval = grid_f(fc);

    const float TWO_PI = 6.283185307179586476925f;
    const float w0 = TWO_PI * fval / fs[b0];
    const float w1 = TWO_PI * fval / fs[b1];
    float c0, sn0, c1, sn1;
    sincosf(w0, &sn0, &c0);
    sincosf(w1, &sn1, &c1);

    // rotation angles for the two chains: phi = -w * (n0 + SEGLEN - 1)
    const float nrotA = (float)((2 * sp)     * SEGLEN + SEGLEN - 1);
    const float nrotB = (float)((2 * sp + 1) * SEGLEN + SEGLEN - 1);
    float rcA0, rsA0, rcA1, rsA1, rcB0, rsB0, rcB1, rsB1;
    sincosf(-w0 * nrotA, &rsA0, &rcA0);
    sincosf(-w1 * nrotA, &rsA1, &rcA1);
    sincosf(-w0 * nrotB, &rsB0, &rcB0);
    sincosf(-w1 * nrotB, &rsB1, &rcB1);

    // ---- load & pack x: 2 samples per ulonglong2 entry ----
    const float2* __restrict__ x0v = (const float2*)(x + b0 * NLEN);
    const float2* __restrict__ x1v = (const float2*)(x + b1 * NLEN);
    for (int i = tid; i < NLEN / 2; i += 256) {
        const float2 a = x0v[i];
        const float2 b = x1v[i];
        ulonglong2 v;
        v.x = pk2(a.x, b.x);
        v.y = pk2(a.y, b.y);
        sx2[i] = v;
    }
    if (tid < (NPAD - NLEN) / 2 + 2) {       // zero-pad 750,751 + 2 spares
        ulonglong2 z; z.x = 0ull; z.y = 0ull;
        sx2[NLEN / 2 + tid] = z;
    }
    __syncthreads();

    const unsigned long long coeff = pk2(2.0f * c0, 2.0f * c1);
    const unsigned long long NEG1  = pk2(-1.0f, -1.0f);
    unsigned long long s1A = 0ull, s2A = 0ull;
    unsigned long long s1B = 0ull, s2B = 0ull;

    const ulonglong2* __restrict__ pA = sx2 + (2 * sp) * SEGU2;
    const ulonglong2* __restrict__ pB = pA + SEGU2;

    // software-pipelined main loop: prefetch i+1 while computing on i
    ulonglong2 vA = pA[0];
    ulonglong2 vB = pB[0];
    #pragma unroll 2
    for (int i = 0; i < SEGU2; i++) {
        const ulonglong2 nA = pA[i + 1];     // spare slot makes tail read safe
        const ulonglong2 nB = pB[i + 1];
        unsigned long long t, s;
        // two independent Goertzel chains, interleaved (ILP=2)
        t = fma2(s2A, NEG1, vA.x);  s = fma2(coeff, s1A, t);  s2A = s1A; s1A = s;
        t = fma2(s2B, NEG1, vB.x);  s = fma2(coeff, s1B, t);  s2B = s1B; s1B = s;
        t = fma2(s2A, NEG1, vA.y);  s = fma2(coeff, s1A, t);  s2A = s1A; s1A = s;
        t = fma2(s2B, NEG1, vB.y);  s = fma2(coeff, s1B, t);  s2B = s1B; s1B = s;
        vA = nA;
        vB = nB;
    }

    // ---- epilogue: P = (s1 - c*s2) + j(sin*s2), rotated, chains summed ----
    float aA0, aA1, dA0, dA1, aB0, aB1, dB0, dB1;
    upk2(s1A, aA0, aA1); upk2(s2A, dA0, dA1);
    upk2(s1B, aB0, aB1); upk2(s2B, dB0, dB1);

    const float greA0 = aA0 - c0 * dA0, gimA0 = sn0 * dA0;
    const float greA1 = aA1 - c1 * dA1, gimA1 = sn1 * dA1;
    const float greB0 = aB0 - c0 * dB0, gimB0 = sn0 * dB0;
    const float greB1 = aB1 - c1 * dB1, gimB1 = sn1 * dB1;

    float4 r;
    r.x = (rcA0 * greA0 - rsA0 * gimA0) + (rcB0 * greB0 - rsB0 * gimB0);  // b0 Re
    r.y = (rcA0 * gimA0 + rsA0 * greA0) + (rcB0 * gimB0 + rsB0 * greB0);  // b0 Im
    r.z = (rcA1 * greA1 - rsA1 * gimA1) + (rcB1 * greB1 - rsB1 * gimB1);  // b1 Re
    r.w = (rcA1 * gimA1 + rsA1 * greA1) + (rcB1 * gimB1 + rsB1 * greB1);  // b1 Im

    __syncthreads();                         // sx2 dead; red overlay takes over
    if (sp > 0) red[(sp - 1) * FCHUNK + fl] = r;
    __syncthreads();

    if (sp == 0 && f < NFREQ) {
        #pragma unroll
        for (int s = 0; s < 3; s++) {
            const float4 o = red[s * FCHUNK + fl];
            r.x += o.x; r.y += o.y; r.z += o.z; r.w += o.w;
        }
        g_psd[b0 * NFREQ_P + f] = r.x * r.x + r.y * r.y;
        g_psd[b1 * NFREQ_P + f] = r.z * r.z + r.w * r.w;
    }

    // ======================================================================
    // Stage 2: elect the last block of this batch pair
    // ======================================================================
    __threadfence();                          // publish psd stores
    __syncthreads();
    if (tid == 0)
        sflag = (atomicAdd(&g_pair_ticket[bp], 1u) == NCHUNKS - 1) ? 1 : 0;
    __syncthreads();
    if (!sflag) return;
    if (tid == 0) g_pair_ticket[bp] = 0;      // self-reset for graph replay

    // 256 threads split: lower 128 -> batch b0, upper 128 -> batch b1
    const int grp = tid >> 7;                 // 0 or 1
    const int lt  = tid & 127;
    const int myb = grp ? b1 : b0;
    const float* __restrict__ psd = g_psd + myb * NFREQ_P;
    float* sred = grp ? sredB : sredA;        // 8-wide scratch; warps 0-3 / 4-7

    // ---- pass 1: max (L2 reads, MLP ~10) ----
    float m = -1e30f;
    for (int ff = lt; ff < NFREQ; ff += 128)
        m = fmaxf(m, __ldcg(psd + ff));
    #pragma unroll
    for (int o = 16; o > 0; o >>= 1)
        m = fmaxf(m, __shfl_down_sync(0xffffffffu, m, o));
    if ((tid & 31) == 0) sredA[tid >> 5] = m; // all 8 warps use sredA slots 0..7
    __syncthreads();
    if (lt == 0) {
        const int base = grp * 4;
        float M = sredA[base];
        #pragma unroll
        for (int w = 1; w < 4; w++) M = fmaxf(M, sredA[base + w]);
        sM2[grp] = M;
    }
    __syncthreads();
    const float M = sM2[grp];

    // ---- pass 2: sum(exp(psd-M)) + argmin |grid - f_true| ----
    const float ft = f_true[myb];
    float se = 0.0f;
    float bd = 1e30f;
    int   bi = NFREQ;
    for (int ff = lt; ff < NFREQ; ff += 128) {
        se += expf(__ldcg(psd + ff) - M);
        const float d = fabsf(grid_f(ff) - ft);
        if (d < bd) { bd = d; bi = ff; }      // strict <: first occurrence/lane
    }
    #pragma unroll
    for (int o = 16; o > 0; o >>= 1) {
        se += __shfl_down_sync(0xffffffffu, se, o);
        const float od = __shfl_down_sync(0xffffffffu, bd, o);
        const int   oi = __shfl_down_sync(0xffffffffu, bi, o);
        if (od < bd || (od == bd && oi < bi)) { bd = od; bi = oi; }
    }
    if ((tid & 31) == 0) {
        const int w = tid >> 5;
        sredB[w] = se; sbd[w] = bd; sidx[w] = bi;
    }
    __syncthreads();

    if (lt == 0) {
        const int base = grp * 4;
        float S = 0.0f, fbd = 1e30f;
        int   fbi = NFREQ;
        #pragma unroll
        for (int w = 0; w < 4; w++) {
            S += sredB[base + w];
            if (sbd[base + w] < fbd ||
                (sbd[base + w] == fbd && sidx[base + w] < fbi)) {
                fbd = sbd[base + w]; fbi = sidx[base + w];
            }
        }
        const float p = expf(__ldcg(psd + fbi) - M) / S;   // softmax[idx]
        g_per[myb] = -logf(p + 1e-8f);
    }

    // ======================================================================
    // Stage 3: last pair overall computes the mean
    // ======================================================================
    __threadfence();
    __syncthreads();
    if (tid == 0)
        sflag = (atomicAdd(&g_ticket, 1u) == BATCH / 2 - 1) ? 1 : 0;
    __syncthreads();
    if (!sflag) return;

    if (tid < BATCH) {
        float v = __ldcg(&g_per[tid]);
        #pragma unroll
        for (int o = 16; o > 0; o >>= 1)
            v += __shfl_down_sync(0xffffffffu, v, o);
        if ((tid & 31) == 0) sredA[tid >> 5] = v;
    }
    __syncthreads();
    if (tid == 0) {
        out[0] = (sredA[0] + sredA[1]) * (1.0f / (float)BATCH);
        g_ticket = 0;                         // self-reset for graph replay
    }
}

// ============================================================================
extern "C" void kernel_launch(void* const* d_in, const int* in_sizes, int n_in,
                              void* d_out, int out_size)
{
    const float* x      = (const float*)d_in[0];   // [64, 1500]
    const float* f_true = (const float*)d_in[1];   // [64]
    const float* fs     = (const float*)d_in[2];   // [64]
    float* out = (float*)d_out;                    // scalar

    dim3 g1(NCHUNKS, BATCH / 2);                   // (20, 32)
    fused_kernel<<<g1, 256>>>(x, fs, f_true, out);
}

// round 9
// speedup vs baseline: 1.1780x; 1.1780x over previous
#include <cuda_runtime.h>
#include <math.h>

#define BATCH    64
#define NLEN     1500
#define NFREQ    1251
#define NFREQ_P  1252
#define FCHUNK   64
#define NCHUNKS  ((NFREQ + FCHUNK - 1) / FCHUNK)    // 20
#define SEG      16
#define SEGLEN   94                                  // 16*94 = 1504 >= 1500
#define NPAD     (SEG * SEGLEN)                      // 1504
#define SEGU2    (SEGLEN / 2)                        // 47 ulonglong2 per segment

__device__ float  g_psd[BATCH * NFREQ_P];
__device__ float2 g_part[BATCH * NCHUNKS * 2];       // per-(batch,chunk,warp) (max, sumexp)

// ---- packed f32x2 helpers (sm_103a) ----
__device__ __forceinline__ unsigned long long pk2(float lo, float hi) {
    unsigned long long r;
    asm("mov.b64 %0, {%1, %2};" : "=l"(r) : "f"(lo), "f"(hi));
    return r;
}
__device__ __forceinline__ void upk2(unsigned long long v, float& lo, float& hi) {
    asm("mov.b64 {%0, %1}, %2;" : "=f"(lo), "=f"(hi) : "l"(v));
}
__device__ __forceinline__ unsigned long long fma2(unsigned long long a,
                                                   unsigned long long b,
                                                   unsigned long long c) {
    unsigned long long d;
    asm("fma.rn.f32x2 %0, %1, %2, %3;" : "=l"(d) : "l"(a), "l"(b), "l"(c));
    return d;
}

// Frequency grid value, matching jnp.arange semantics: iota*step + start in f32
__device__ __forceinline__ float grid_f(int i) {
    return __fadd_rn(__fmul_rn((float)i, 0.002f), 0.5f);
}

// ============================================================================
// Kernel 1: segmented Goertzel PSD, 4 independent chains per thread (ILP=4:
// one warp alone oversubscribes the fma pipe 4x, so the 4-cycle RAW latency
// and the LDS latency are fully hidden even at low occupancy).
// Block = (batch pair, 64-freq chunk), 256 threads = 64 freq lanes x 4
// segment-quads; both batches packed in f32x2 lanes. After the PSD, each
// warp of sp==0 emits a chunk-local (max, sumexp) partial for the softmax,
// so the downstream work is O(BATCH*NCHUNKS) instead of O(BATCH*NFREQ).
// ============================================================================
__global__ void __launch_bounds__(256)
goertzel_kernel(const float* __restrict__ x, const float* __restrict__ fs)
{
    // 753 entries: 752 data (+pad) + 1 spare so tail prefetch stays in bounds
    __shared__ __align__(16) char smem_raw[(NPAD / 2 + 1) * 16];
    ulonglong2* sx2 = (ulonglong2*)smem_raw;
    float4*     red = (float4*)smem_raw;     // overlaid AFTER sx2 is dead

    const int tid = threadIdx.x;
    const int bp  = blockIdx.y;              // batch pair 0..31
    const int b0  = 2 * bp;
    const int b1  = 2 * bp + 1;

    const int fl  = tid & (FCHUNK - 1);      // frequency lane 0..63
    const int sp  = tid >> 6;                // segment quad 0..3
    const int f   = blockIdx.x * FCHUNK + fl;
    const int fc  = (f < NFREQ) ? f : (NFREQ - 1);
    const float fval = grid_f(fc);

    const float TWO_PI = 6.283185307179586476925f;
    const float w0 = TWO_PI * fval / fs[b0];
    const float w1 = TWO_PI * fval / fs[b1];
    float c0, sn0, c1, sn1;
    sincosf(w0, &sn0, &c0);
    sincosf(w1, &sn1, &c1);

    // rotation for chain 0 of this quad: phi = -w * (4sp*SEGLEN + SEGLEN-1),
    // and the per-chain step psi = -w * SEGLEN (applied incrementally).
    const float nrot0 = (float)(4 * sp * SEGLEN + SEGLEN - 1);
    float rc0, rs0, rc1, rs1, pc0, ps0, pc1, ps1;
    sincosf(-w0 * nrot0, &rs0, &rc0);
    sincosf(-w1 * nrot0, &rs1, &rc1);
    sincosf(-w0 * (float)SEGLEN, &ps0, &pc0);
    sincosf(-w1 * (float)SEGLEN, &ps1, &pc1);

    // ---- load & pack x: 2 samples per ulonglong2 entry ----
    const float2* __restrict__ x0v = (const float2*)(x + b0 * NLEN);
    const float2* __restrict__ x1v = (const float2*)(x + b1 * NLEN);
    for (int i = tid; i < NLEN / 2; i += 256) {
        const float2 a = x0v[i];
        const float2 b = x1v[i];
        ulonglong2 v;
        v.x = pk2(a.x, b.x);
        v.y = pk2(a.y, b.y);
        sx2[i] = v;
    }
    if (tid < (NPAD - NLEN) / 2 + 1) {       // zero entries 750,751 + spare 752
        ulonglong2 z; z.x = 0ull; z.y = 0ull;
        sx2[NLEN / 2 + tid] = z;
    }
    __syncthreads();

    const unsigned long long coeff = pk2(2.0f * c0, 2.0f * c1);
    const unsigned long long NEG1  = pk2(-1.0f, -1.0f);
    unsigned long long s1A = 0ull, s2A = 0ull, s1B = 0ull, s2B = 0ull;
    unsigned long long s1C = 0ull, s2C = 0ull, s1D = 0ull, s2D = 0ull;

    const ulonglong2* __restrict__ pA = sx2 + (4 * sp) * SEGU2;
    const ulonglong2* __restrict__ pB = pA + SEGU2;
    const ulonglong2* __restrict__ pC = pB + SEGU2;
    const ulonglong2* __restrict__ pD = pC + SEGU2;

    // software-pipelined: prefetch i+1 while computing on i (all loads are
    // warp-uniform addresses -> SMEM broadcast, no crossbar pressure)
    ulonglong2 vA = pA[0], vB = pB[0], vC = pC[0], vD = pD[0];
    for (int i = 0; i < SEGU2; i++) {
        const ulonglong2 nA = pA[i + 1];
        const ulonglong2 nB = pB[i + 1];
        const ulonglong2 nC = pC[i + 1];
        const ulonglong2 nD = pD[i + 1];
        unsigned long long t, s;
        // four independent Goertzel chains, interleaved (ILP=4)
        t = fma2(s2A, NEG1, vA.x);  s = fma2(coeff, s1A, t);  s2A = s1A; s1A = s;
        t = fma2(s2B, NEG1, vB.x);  s = fma2(coeff, s1B, t);  s2B = s1B; s1B = s;
        t = fma2(s2C, NEG1, vC.x);  s = fma2(coeff, s1C, t);  s2C = s1C; s1C = s;
        t = fma2(s2D, NEG1, vD.x);  s = fma2(coeff, s1D, t);  s2D = s1D; s1D = s;
        t = fma2(s2A, NEG1, vA.y);  s = fma2(coeff, s1A, t);  s2A = s1A; s1A = s;
        t = fma2(s2B, NEG1, vB.y);  s = fma2(coeff, s1B, t);  s2B = s1B; s1B = s;
        t = fma2(s2C, NEG1, vC.y);  s = fma2(coeff, s1C, t);  s2C = s1C; s1C = s;
        t = fma2(s2D, NEG1, vD.y);  s = fma2(coeff, s1D, t);  s2D = s1D; s1D = s;
        vA = nA; vB = nB; vC = nC; vD = nD;
    }

    // ---- epilogue: per chain P = (s1 - c*s2) + j(sin*s2), rotate & sum ----
    float accRe0 = 0.0f, accIm0 = 0.0f, accRe1 = 0.0f, accIm1 = 0.0f;
    unsigned long long s1s[4] = {s1A, s1B, s1C, s1D};
    unsigned long long s2s[4] = {s2A, s2B, s2C, s2D};
    #pragma unroll
    for (int cch = 0; cch < 4; cch++) {
        float a0, a1, d0, d1;
        upk2(s1s[cch], a0, a1);
        upk2(s2s[cch], d0, d1);
        const float gre0 = a0 - c0 * d0, gim0 = sn0 * d0;
        const float gre1 = a1 - c1 * d1, gim1 = sn1 * d1;
        accRe0 += rc0 * gre0 - rs0 * gim0;
        accIm0 += rc0 * gim0 + rs0 * gre0;
        accRe1 += rc1 * gre1 - rs1 * gim1;
        accIm1 += rc1 * gim1 + rs1 * gre1;
        // advance rotation by psi
        const float trc0 = rc0 * pc0 - rs0 * ps0;
        rs0 = rc0 * ps0 + rs0 * pc0;  rc0 = trc0;
        const float trc1 = rc1 * pc1 - rs1 * ps1;
        rs1 = rc1 * ps1 + rs1 * pc1;  rc1 = trc1;
    }

    float4 r;
    r.x = accRe0; r.y = accIm0; r.z = accRe1; r.w = accIm1;

    __syncthreads();                         // sx2 dead; red overlay takes over
    if (sp > 0) red[(sp - 1) * FCHUNK + fl] = r;
    __syncthreads();

    if (sp == 0) {
        #pragma unroll
        for (int s = 0; s < 3; s++) {
            const float4 o = red[s * FCHUNK + fl];
            r.x += o.x; r.y += o.y; r.z += o.z; r.w += o.w;
        }
        const bool valid = (f < NFREQ);
        float p0 = r.x * r.x + r.y * r.y;
        float p1 = r.z * r.z + r.w * r.w;
        if (valid) {
            g_psd[b0 * NFREQ_P + f] = p0;
            g_psd[b1 * NFREQ_P + f] = p1;
        } else {
            p0 = -1e30f; p1 = -1e30f;        // neutral for max; exp -> 0
        }

        // ---- chunk-local softmax partials: per-warp (max, sumexp) ----
        float m0 = p0, m1 = p1;
        #pragma unroll
        for (int o = 16; o > 0; o >>= 1) {
            m0 = fmaxf(m0, __shfl_xor_sync(0xffffffffu, m0, o));
            m1 = fmaxf(m1, __shfl_xor_sync(0xffffffffu, m1, o));
        }
        float e0 = expf(p0 - m0);
        float e1 = expf(p1 - m1);
        #pragma unroll
        for (int o = 16; o > 0; o >>= 1) {
            e0 += __shfl_xor_sync(0xffffffffu, e0, o);
            e1 += __shfl_xor_sync(0xffffffffu, e1, o);
        }
        if ((tid & 31) == 0) {
            const int w = tid >> 5;          // 0 or 1
            g_part[(b0 * NCHUNKS + blockIdx.x) * 2 + w] = make_float2(m0, e0);
            g_part[(b1 * NCHUNKS + blockIdx.x) * 2 + w] = make_float2(m1, e1);
        }
    }
}

// ============================================================================
// Kernel 2: finalize. One 64-thread block; thread b merges its 40 chunk
// partials (exact logsumexp merge), finds the argmin grid index analytically
// (monotone grid: search +/-4 around round((ft-0.5)*500)), computes the
// per-sample loss, and the block reduces the mean.
// ============================================================================
__global__ void __launch_bounds__(64)
finalize_kernel(const float* __restrict__ f_true, float* __restrict__ out)
{
    const int b = threadIdx.x;               // 0..63
    const float2* __restrict__ part = g_part + b * NCHUNKS * 2;

    float M = -1e30f;
    #pragma unroll
    for (int i = 0; i < NCHUNKS * 2; i++)
        M = fmaxf(M, part[i].x);
    float S = 0.0f;
    #pragma unroll
    for (int i = 0; i < NCHUNKS * 2; i++)
        S += part[i].y * expf(part[i].x - M);

    // ---- analytic argmin of |grid_f(k) - ft| (first occurrence) ----
    const float ft = f_true[b];
    int k0 = (int)lrintf((ft - 0.5f) * 500.0f);
    k0 = min(max(k0, 0), NFREQ - 1);
    const int klo = max(k0 - 4, 0);
    const int khi = min(k0 + 4, NFREQ - 1);
    float bd = 1e30f;
    int   bi = klo;
    for (int k = klo; k <= khi; k++) {        // ascending: strict < keeps first
        const float d = fabsf(grid_f(k) - ft);
        if (d < bd) { bd = d; bi = k; }
    }

    const float p = expf(g_psd[b * NFREQ_P + bi] - M) / S;   // softmax[idx]
    float v = -logf(p + 1e-8f);

    // ---- mean over 64 ----
    #pragma unroll
    for (int o = 16; o > 0; o >>= 1)
        v += __shfl_down_sync(0xffffffffu, v, o);
    __shared__ float sw[2];
    if ((b & 31) == 0) sw[b >> 5] = v;
    __syncthreads();
    if (b == 0)
        out[0] = (sw[0] + sw[1]) * (1.0f / (float)BATCH);
}

// ============================================================================
extern "C" void kernel_launch(void* const* d_in, const int* in_sizes, int n_in,
                              void* d_out, int out_size)
{
    const float* x      = (const float*)d_in[0];   // [64, 1500]
    const float* f_true = (const float*)d_in[1];   // [64]
    const float* fs     = (const float*)d_in[2];   // [64]
    float* out = (float*)d_out;                    // scalar

    dim3 g1(NCHUNKS, BATCH / 2);                   // (20, 32)
    goertzel_kernel<<<g1, 256>>>(x, fs);
    finalize_kernel<<<1, 64>>>(f_true, out);
}